// round 3
// baseline (speedup 1.0000x reference)
#include <cuda_runtime.h>
#include <math.h>

#define HW      65536
#define BATCH   4

// ---------------- scratch (device globals; no allocation allowed) ----------
__device__ float g_out1[(size_t)BATCH * 64  * HW];   //  64 MB  conv1x1 #1 out
__device__ float g_cat [(size_t)BATCH * 256 * HW];   // 256 MB  4-direction scan concat
__device__ float g_out2[(size_t)BATCH * 64  * HW];   //  64 MB  conv1x1 #2 out
__device__ float g_a1  [(size_t)BATCH * 32  * HW];   //  32 MB
__device__ float g_a2  [(size_t)BATCH * 32  * HW];   //  32 MB

// ---------------------------------------------------------------------------
// SGEMM: Y[b][m][p] = (relu?)( sum_k Wt[m][k] * X[b][k][p] ),  m in [0,64)
// Block tile 64M x 256N, Ktile 16, 256 threads, 8x8 per-thread tile.
// grid = (HW/256, 1, BATCH)
// ---------------------------------------------------------------------------
template<int K, bool RELU>
__global__ __launch_bounds__(256)
void k_gemm64(const float* __restrict__ Wt, const float* __restrict__ X,
              float* __restrict__ Y)
{
    __shared__ float xs[16][256];
    __shared__ float wsT[64 * 17];      // [m][k] padded stride 17

    const int tid  = threadIdx.x;
    const int n0   = blockIdx.x * 256;
    const int b    = blockIdx.z;
    const float* Xb = X + (size_t)b * K * HW;
    float*       Yb = Y + (size_t)b * 64 * HW;

    const int mg   = tid >> 5;          // 0..7
    const int lane = tid & 31;
    const int m0   = mg * 8;

    float acc[8][8];
#pragma unroll
    for (int i = 0; i < 8; i++)
#pragma unroll
        for (int j = 0; j < 8; j++) acc[i][j] = 0.f;

    for (int kt = 0; kt < K; kt += 16) {
        // W tile: 64x16, transposed-to-[m][k] in smem
#pragma unroll
        for (int r = 0; r < 4; r++) {
            int e  = tid + r * 256;
            int m  = e >> 4;
            int kk = e & 15;
            wsT[m * 17 + kk] = Wt[m * K + kt + kk];
        }
        // X tile: 16x256, fully coalesced (one row per iteration)
#pragma unroll
        for (int r = 0; r < 16; r++)
            xs[r][tid] = Xb[(size_t)(kt + r) * HW + n0 + tid];
        __syncthreads();

#pragma unroll
        for (int k = 0; k < 16; k++) {
            float4 xa = *(const float4*)&xs[k][lane * 4];
            float4 xb = *(const float4*)&xs[k][128 + lane * 4];
            float wv[8];
#pragma unroll
            for (int j = 0; j < 8; j++) wv[j] = wsT[(m0 + j) * 17 + k];
#pragma unroll
            for (int j = 0; j < 8; j++) {
                acc[j][0] = fmaf(wv[j], xa.x, acc[j][0]);
                acc[j][1] = fmaf(wv[j], xa.y, acc[j][1]);
                acc[j][2] = fmaf(wv[j], xa.z, acc[j][2]);
                acc[j][3] = fmaf(wv[j], xa.w, acc[j][3]);
                acc[j][4] = fmaf(wv[j], xb.x, acc[j][4]);
                acc[j][5] = fmaf(wv[j], xb.y, acc[j][5]);
                acc[j][6] = fmaf(wv[j], xb.z, acc[j][6]);
                acc[j][7] = fmaf(wv[j], xb.w, acc[j][7]);
            }
        }
        __syncthreads();
    }

#pragma unroll
    for (int j = 0; j < 8; j++) {
        float4 va, vb;
        va.x = acc[j][0]; va.y = acc[j][1]; va.z = acc[j][2]; va.w = acc[j][3];
        vb.x = acc[j][4]; vb.y = acc[j][5]; vb.z = acc[j][6]; vb.w = acc[j][7];
        if (RELU) {
            va.x = fmaxf(va.x, 0.f); va.y = fmaxf(va.y, 0.f);
            va.z = fmaxf(va.z, 0.f); va.w = fmaxf(va.w, 0.f);
            vb.x = fmaxf(vb.x, 0.f); vb.y = fmaxf(vb.y, 0.f);
            vb.z = fmaxf(vb.z, 0.f); vb.w = fmaxf(vb.w, 0.f);
        }
        *(float4*)&Yb[(size_t)(m0 + j) * HW + n0 + lane * 4]       = va;
        *(float4*)&Yb[(size_t)(m0 + j) * HW + n0 + 128 + lane * 4] = vb;
    }
}

// ---------------------------------------------------------------------------
// Vertical IRNN scans (down: forward over H -> cat dir 2; up: reverse -> dir 0)
// One thread per (b, c, w) column. 65536 threads. Loads/stores coalesced.
// cat layout: [b][dir*64 + c][h][w],  dirs: up=0, right=1, down=2, left=3
// ---------------------------------------------------------------------------
__global__ __launch_bounds__(256)
void k_scan_v(const float* __restrict__ src, float* __restrict__ cat,
              const float* __restrict__ w_up, const float* __restrict__ b_up,
              const float* __restrict__ w_dn, const float* __restrict__ b_dn)
{
    int idx = blockIdx.x * 256 + threadIdx.x;     // [0, 65536)
    int w = idx & 255;
    int c = (idx >> 8) & 63;
    int b = idx >> 14;

    const float* s  = src + (((size_t)b * 64 + c) << 16) + w;
    float* cu = cat + (((size_t)b * 256 +   0 + c) << 16) + w;
    float* cd = cat + (((size_t)b * 256 + 128 + c) << 16) + w;

    float Wd = w_dn[c], Bd = b_dn[c], Wu = w_up[c], Bu = b_up[c];

    float h = 0.f;
    for (int r = 0; r < 256; r++) {
        h = fmaxf(fmaf(Wd, h, s[r << 8] + Bd), 0.f);
        cd[r << 8] = h;
    }
    h = 0.f;
    for (int r = 255; r >= 0; r--) {
        h = fmaxf(fmaf(Wu, h, s[r << 8] + Bu), 0.f);
        cu[r << 8] = h;
    }
}

// ---------------------------------------------------------------------------
// Horizontal IRNN scans (right: forward over W -> dir 1; left: reverse -> dir 3)
// One thread per (b, c, h) row. Sequential 4B accesses per thread reuse each
// 32B sector over 8 steps -> no real traffic inflation (L1 resident).
// ---------------------------------------------------------------------------
__global__ __launch_bounds__(256)
void k_scan_h(const float* __restrict__ src, float* __restrict__ cat,
              const float* __restrict__ w_rt, const float* __restrict__ b_rt,
              const float* __restrict__ w_lt, const float* __restrict__ b_lt)
{
    int idx = blockIdx.x * 256 + threadIdx.x;     // [0, 65536)
    int hrow = idx & 255;
    int c = (idx >> 8) & 63;
    int b = idx >> 14;

    const float* s  = src + (((size_t)b * 64 + c) << 16) + hrow * 256;
    float* cr = cat + (((size_t)b * 256 +  64 + c) << 16) + hrow * 256;
    float* cl = cat + (((size_t)b * 256 + 192 + c) << 16) + hrow * 256;

    float Wr = w_rt[c], Br = b_rt[c], Wl = w_lt[c], Bl = b_lt[c];

    float h = 0.f;
    for (int w = 0; w < 256; w++) {
        h = fmaxf(fmaf(Wr, h, s[w] + Br), 0.f);
        cr[w] = h;
    }
    h = 0.f;
    for (int w = 255; w >= 0; w--) {
        h = fmaxf(fmaf(Wl, h, s[w] + Bl), 0.f);
        cl[w] = h;
    }
}

// ---------------------------------------------------------------------------
// 3x3 conv, SAME padding, CI -> 32 channels, relu(out + bias).
// One block per (h, b) = full 256-pixel row.  256 threads.
// Per input channel: stage 3 halo rows (258 valid, pad 264) + 9x32 weights
// in smem; per-thread tile 8 outch x 4 pixels.
// grid = (256, 1, BATCH)
// ---------------------------------------------------------------------------
template<int CI>
__global__ __launch_bounds__(256)
void k_conv3(const float* __restrict__ in, const float* __restrict__ wt,
             const float* __restrict__ bias, float* __restrict__ out)
{
    __shared__ float xsr[3 * 264];
    __shared__ float wsm[9 * 32];

    const int h   = blockIdx.x;
    const int b   = blockIdx.z;
    const int tid = threadIdx.x;
    const int o0  = (tid >> 6) * 8;     // 0,8,16,24  (constant per warp)
    const int ng  = tid & 63;
    const int n   = ng * 4;

    const float* inb = in + (size_t)b * CI * HW;

    float acc[8][4];
#pragma unroll
    for (int oo = 0; oo < 8; oo++) {
        float bv = bias[o0 + oo];
#pragma unroll
        for (int j = 0; j < 4; j++) acc[oo][j] = bv;
    }

    for (int i = 0; i < CI; i++) {
        // stage 3 input rows (h-1, h, h+1), columns -1..256 -> wp 0..257
        for (int e = tid; e < 3 * 264; e += 256) {
            int r  = e / 264;
            int wp = e - r * 264;
            int hh = h + r - 1;
            int ww = wp - 1;
            float v = 0.f;
            if (wp < 258 && (unsigned)hh < 256u && (unsigned)ww < 256u)
                v = inb[(size_t)i * HW + hh * 256 + ww];
            xsr[e] = v;
        }
        // stage weights: wsm[tap][o]
        for (int e = tid; e < 288; e += 256) {
            int tap = e >> 5, o = e & 31;
            wsm[e] = wt[((size_t)o * CI + i) * 9 + tap];
        }
        __syncthreads();

#pragma unroll
        for (int r = 0; r < 3; r++) {
            float4 xq = *(const float4*)&xsr[r * 264 + n];
            float  x4 = xsr[r * 264 + n + 4];
            float  x5 = xsr[r * 264 + n + 5];
            float xv[6] = {xq.x, xq.y, xq.z, xq.w, x4, x5};
#pragma unroll
            for (int c = 0; c < 3; c++) {
                int tap = r * 3 + c;
                float4 wa = *(const float4*)&wsm[tap * 32 + o0];
                float4 wb = *(const float4*)&wsm[tap * 32 + o0 + 4];
                float wv[8] = {wa.x, wa.y, wa.z, wa.w, wb.x, wb.y, wb.z, wb.w};
#pragma unroll
                for (int j = 0; j < 4; j++) {
                    float xvv = xv[c + j];
#pragma unroll
                    for (int oo = 0; oo < 8; oo++)
                        acc[oo][j] = fmaf(wv[oo], xvv, acc[oo][j]);
                }
            }
        }
        __syncthreads();
    }

#pragma unroll
    for (int oo = 0; oo < 8; oo++) {
        float4 v;
        v.x = fmaxf(acc[oo][0], 0.f);
        v.y = fmaxf(acc[oo][1], 0.f);
        v.z = fmaxf(acc[oo][2], 0.f);
        v.w = fmaxf(acc[oo][3], 0.f);
        *(float4*)&out[((size_t)(b * 32 + o0 + oo)) * HW + h * 256 + n] = v;
    }
}

// ---------------------------------------------------------------------------
// Final: a = a3_w . a2 + a3_b ; weight = sigmoid(a) ; out = relu(x * weight)
// One thread per pixel.
// ---------------------------------------------------------------------------
__global__ __launch_bounds__(256)
void k_final(const float* __restrict__ a2buf, const float* __restrict__ a3w,
             const float* __restrict__ a3b, const float* __restrict__ x,
             float* __restrict__ out)
{
    int p  = blockIdx.x * 256 + threadIdx.x;     // [0, 262144)
    int b  = p >> 16;
    int hw = p & 65535;

    const float* ab = a2buf + ((size_t)b * 32) * HW + hw;
    float s = a3b[0];
#pragma unroll
    for (int c = 0; c < 32; c++)
        s = fmaf(a3w[c], ab[(size_t)c * HW], s);

    float wgt = 1.f / (1.f + expf(-s));

    const float* xb = x   + ((size_t)b * 64) * HW + hw;
    float*       ob = out + ((size_t)b * 64) * HW + hw;
#pragma unroll 8
    for (int c = 0; c < 64; c++)
        ob[(size_t)c * HW] = fmaxf(xb[(size_t)c * HW] * wgt, 0.f);
}

// ---------------------------------------------------------------------------
extern "C" void kernel_launch(void* const* d_in, const int* in_sizes, int n_in,
                              void* d_out, int out_size)
{
    const float* x       = (const float*)d_in[0];
    const float* w_in    = (const float*)d_in[1];
    const float* w_up    = (const float*)d_in[2];
    const float* b_up    = (const float*)d_in[3];
    const float* w_right = (const float*)d_in[4];
    const float* b_right = (const float*)d_in[5];
    const float* w_down  = (const float*)d_in[6];
    const float* b_down  = (const float*)d_in[7];
    const float* w_left  = (const float*)d_in[8];
    const float* b_left  = (const float*)d_in[9];
    const float* wD2     = (const float*)d_in[10];
    const float* a1_w    = (const float*)d_in[11];
    const float* a1_b    = (const float*)d_in[12];
    const float* a2_w    = (const float*)d_in[13];
    const float* a2_b    = (const float*)d_in[14];
    const float* a3_w    = (const float*)d_in[15];
    const float* a3_b    = (const float*)d_in[16];
    float* out = (float*)d_out;

    float *p_out1, *p_cat, *p_out2, *p_a1, *p_a2;
    cudaGetSymbolAddress((void**)&p_out1, g_out1);
    cudaGetSymbolAddress((void**)&p_cat,  g_cat);
    cudaGetSymbolAddress((void**)&p_out2, g_out2);
    cudaGetSymbolAddress((void**)&p_a1,   g_a1);
    cudaGetSymbolAddress((void**)&p_a2,   g_a2);

    dim3 gGemm(HW / 256, 1, BATCH);      // (256,1,4)
    dim3 gConv(256, 1, BATCH);

    // 1) out1 = conv1x1(x, w_in)                 (no relu)
    k_gemm64<64, false><<<gGemm, 256>>>(w_in, x, p_out1);

    // 2) four directional IRNN scans -> cat [b][4*64][h][w]
    k_scan_v<<<256, 256>>>(p_out1, p_cat, w_up, b_up, w_down, b_down);
    k_scan_h<<<256, 256>>>(p_out1, p_cat, w_right, b_right, w_left, b_left);

    // 3) out2 = relu(conv1x1(cat, wD2))          K = 256
    k_gemm64<256, true><<<gGemm, 256>>>(wD2, p_cat, p_out2);

    // 4) a1 = relu(conv3x3(out2, a1_w) + a1_b)
    k_conv3<64><<<gConv, 256>>>(p_out2, a1_w, a1_b, p_a1);

    // 5) a2 = relu(conv3x3(a1, a2_w) + a2_b)
    k_conv3<32><<<gConv, 256>>>(p_a1, a2_w, a2_b, p_a2);

    // 6) out = relu(x * sigmoid(a3_w . a2 + a3_b))
    k_final<<<HW * BATCH / 256, 256>>>(p_a2, a3_w, a3_b, x, out);
}

// round 5
// speedup vs baseline: 1.3318x; 1.3318x over previous
#include <cuda_runtime.h>
#include <math.h>

#define HW      65536
#define BATCH   4

// ---------------- scratch (device globals; no allocation allowed) ----------
__device__ float g_out1[(size_t)BATCH * 64  * HW];   //  64 MB
__device__ float g_cat [(size_t)BATCH * 256 * HW];   // 256 MB
__device__ float g_out2[(size_t)BATCH * 64  * HW];   //  64 MB
__device__ float g_a1  [(size_t)BATCH * 32  * HW];   //  32 MB
__device__ float g_a2  [(size_t)BATCH * 32  * HW];   //  32 MB

// ---------------- tf32 mma helpers ----------------------------------------
__device__ __forceinline__ unsigned f2tf(float f) {
    unsigned u;
    asm("cvt.rna.tf32.f32 %0, %1;" : "=r"(u) : "f"(f));
    return u;
}

#define MMA_TF32(c, a, b0, b1)                                              \
    asm volatile("mma.sync.aligned.m16n8k8.row.col.f32.tf32.tf32.f32 "      \
        "{%0,%1,%2,%3}, {%4,%5,%6,%7}, {%8,%9}, {%0,%1,%2,%3};"             \
        : "+f"((c)[0]), "+f"((c)[1]), "+f"((c)[2]), "+f"((c)[3])            \
        : "r"((a)[0]), "r"((a)[1]), "r"((a)[2]), "r"((a)[3]),               \
          "r"(b0), "r"(b1))

// ---------------------------------------------------------------------------
// TF32 tensor-core GEMM: Y[b][m][p] = (relu?)( sum_k Wt[m][k] * X[b][k][p] )
// m in [0,64). Block: 256 thr (8 warps), tile M64 x N256, Kchunk 32.
// Warp layout: 2 M-groups (32) x 4 N-groups (64). Warp tile: 2x8 mma(16x8).
// grid = (HW/256, 1, BATCH)
// ---------------------------------------------------------------------------
template<int K, bool RELU>
__global__ __launch_bounds__(256)
void k_gemm_tc(const float* __restrict__ Wt, const float* __restrict__ X,
               float* __restrict__ Y)
{
    __shared__ unsigned ws[64 * 36];        // A tile [m][k], stride 36 (conflict-free frag loads)
    __shared__ unsigned xs[32 * 264];       // B tile [k][n], stride 264 (264%32==8)

    const int tid  = threadIdx.x;
    const int warp = tid >> 5;
    const int lane = tid & 31;
    const int n0   = blockIdx.x * 256;
    const int b    = blockIdx.z;
    const float* Xb = X + (size_t)b * K * HW;
    float*       Yb = Y + (size_t)b * 64 * HW;

    const int mw = (warp & 1) * 32;         // warp M base
    const int nw = (warp >> 1) * 64;        // warp N base
    const int qt = lane >> 2;               // groupID
    const int rt = lane & 3;                // threadID-in-group

    float acc[2][8][4];
#pragma unroll
    for (int i = 0; i < 2; i++)
#pragma unroll
        for (int j = 0; j < 8; j++)
#pragma unroll
            for (int v = 0; v < 4; v++) acc[i][j][v] = 0.f;

    for (int kt = 0; kt < K; kt += 32) {
        // stage W: 64x32, coalesced (each warp reads one contiguous 32-row)
#pragma unroll
        for (int r = 0; r < 8; r++) {
            int e  = tid + r * 256;
            int m  = e >> 5;
            int kk = e & 31;
            ws[m * 36 + kk] = f2tf(Wt[m * K + kt + kk]);
        }
        // stage X: 32x256 via float4, coalesced
#pragma unroll
        for (int r = 0; r < 8; r++) {
            int idx = r * 256 + tid;        // 2048 float4
            int k   = idx >> 6;
            int nf  = idx & 63;
            float4 v = *(const float4*)&Xb[(size_t)(kt + k) * HW + n0 + nf * 4];
            unsigned* d = &xs[k * 264 + nf * 4];
            d[0] = f2tf(v.x); d[1] = f2tf(v.y); d[2] = f2tf(v.z); d[3] = f2tf(v.w);
        }
        __syncthreads();

#pragma unroll
        for (int kk = 0; kk < 4; kk++) {
            const int kb = kk * 8;
            unsigned a[2][4];
#pragma unroll
            for (int mt = 0; mt < 2; mt++) {
                int mr = mw + mt * 16 + qt;
                int kc = kb + rt;
                a[mt][0] = ws[mr * 36 + kc];
                a[mt][1] = ws[(mr + 8) * 36 + kc];
                a[mt][2] = ws[mr * 36 + kc + 4];
                a[mt][3] = ws[(mr + 8) * 36 + kc + 4];
            }
#pragma unroll
            for (int nt = 0; nt < 8; nt++) {
                int col = nw + nt * 8 + qt;
                unsigned b0 = xs[(kb + rt) * 264 + col];
                unsigned b1 = xs[(kb + rt + 4) * 264 + col];
                MMA_TF32(acc[0][nt], a[0], b0, b1);
                MMA_TF32(acc[1][nt], a[1], b0, b1);
            }
        }
        __syncthreads();
    }

    // epilogue: c0/c1 -> (row, 2q..2q+1), c2/c3 -> (row+8, same cols)
#pragma unroll
    for (int mt = 0; mt < 2; mt++) {
        int mr = mw + mt * 16 + qt;
#pragma unroll
        for (int nt = 0; nt < 8; nt++) {
            int col = n0 + nw + nt * 8 + rt * 2;
            float2 v0, v1;
            v0.x = acc[mt][nt][0]; v0.y = acc[mt][nt][1];
            v1.x = acc[mt][nt][2]; v1.y = acc[mt][nt][3];
            if (RELU) {
                v0.x = fmaxf(v0.x, 0.f); v0.y = fmaxf(v0.y, 0.f);
                v1.x = fmaxf(v1.x, 0.f); v1.y = fmaxf(v1.y, 0.f);
            }
            *(float2*)&Yb[(size_t)mr * HW + col]       = v0;
            *(float2*)&Yb[(size_t)(mr + 8) * HW + col] = v1;
        }
    }
}

// ---------------------------------------------------------------------------
// TF32 tensor-core 3x3 conv (SAME), CI -> 32 channels, relu(out + bias).
// Implicit GEMM: M=32, K=CI*9 (tap-outer, chunked 8 channels), N=256 (one row).
// Block: 256 thr (8 warps); each warp: full M32 (2 mma-M) x N32 (4 mma-N).
// grid = (256, 1, BATCH)
// ---------------------------------------------------------------------------
template<int CI>
__global__ __launch_bounds__(256)
void k_conv3_tc(const float* __restrict__ in, const float* __restrict__ wt,
                const float* __restrict__ bias, float* __restrict__ out)
{
    __shared__ unsigned xs[8 * 3 * 264];    // [i][r][col] input tf32, halo cols 0..257
    __shared__ unsigned ws[9 * 8 * 40];     // [tap][i][o] weights tf32, i-stride 40 (40%32==8)

    const int h    = blockIdx.x;
    const int b    = blockIdx.z;
    const int tid  = threadIdx.x;
    const int warp = tid >> 5;
    const int lane = tid & 31;
    const int nwb  = warp * 32;             // warp pixel base
    const int qt   = lane >> 2;
    const int rt   = lane & 3;

    const float* inb = in + (size_t)b * CI * HW;

    float acc[2][4][4];
#pragma unroll
    for (int i = 0; i < 2; i++)
#pragma unroll
        for (int j = 0; j < 4; j++)
#pragma unroll
            for (int v = 0; v < 4; v++) acc[i][j][v] = 0.f;

    for (int i0 = 0; i0 < CI; i0 += 8) {
        // stage input: 8 channels x 3 halo rows x cols -1..256 (0-padded)
        for (int e = tid; e < 8 * 3 * 264; e += 256) {
            int i   = e / 792;
            int rem = e - i * 792;
            int r   = rem / 264;
            int col = rem - r * 264;
            int hh  = h + r - 1;
            int ww  = col - 1;
            float v = 0.f;
            if (col < 258 && (unsigned)hh < 256u && (unsigned)ww < 256u)
                v = inb[(size_t)(i0 + i) * HW + hh * 256 + ww];
            xs[e] = f2tf(v);
        }
        // stage weights: ws[tap][i][o] = wt[o][i0+i][tap]
        for (int e = tid; e < 9 * 8 * 32; e += 256) {
            int tap = e >> 8;
            int rem = e & 255;
            int i   = rem >> 5;
            int o   = rem & 31;
            ws[tap * 320 + i * 40 + o] = f2tf(wt[((size_t)o * CI + i0 + i) * 9 + tap]);
        }
        __syncthreads();

#pragma unroll
        for (int tap = 0; tap < 9; tap++) {
            const int r = tap / 3, c = tap % 3;
            unsigned a[2][4];
#pragma unroll
            for (int mt = 0; mt < 2; mt++) {
                int o = mt * 16 + qt;
                a[mt][0] = ws[tap * 320 + rt * 40 + o];
                a[mt][1] = ws[tap * 320 + rt * 40 + o + 8];
                a[mt][2] = ws[tap * 320 + (rt + 4) * 40 + o];
                a[mt][3] = ws[tap * 320 + (rt + 4) * 40 + o + 8];
            }
#pragma unroll
            for (int nt = 0; nt < 4; nt++) {
                int col = nwb + nt * 8 + qt + c;   // output pixel n -> xs col n + c
                unsigned b0 = xs[rt * 792 + r * 264 + col];
                unsigned b1 = xs[(rt + 4) * 792 + r * 264 + col];
                MMA_TF32(acc[0][nt], a[0], b0, b1);
                MMA_TF32(acc[1][nt], a[1], b0, b1);
            }
        }
        __syncthreads();
    }

    // epilogue: bias + relu, float2 stores
#pragma unroll
    for (int mt = 0; mt < 2; mt++) {
        int o  = mt * 16 + qt;
        float bv0 = bias[o];
        float bv1 = bias[o + 8];
#pragma unroll
        for (int nt = 0; nt < 4; nt++) {
            int col = nwb + nt * 8 + rt * 2;
            float2 v0, v1;
            v0.x = fmaxf(acc[mt][nt][0] + bv0, 0.f);
            v0.y = fmaxf(acc[mt][nt][1] + bv0, 0.f);
            v1.x = fmaxf(acc[mt][nt][2] + bv1, 0.f);
            v1.y = fmaxf(acc[mt][nt][3] + bv1, 0.f);
            *(float2*)&out[((size_t)(b * 32 + o))     * HW + h * 256 + col] = v0;
            *(float2*)&out[((size_t)(b * 32 + o + 8)) * HW + h * 256 + col] = v1;
        }
    }
}

// ---------------------------------------------------------------------------
// Vertical IRNN scans (down -> dir 2, up -> dir 0). One thread per (b,c,w).
// cat layout: [b][dir*64 + c][h][w],  dirs: up=0, right=1, down=2, left=3
// ---------------------------------------------------------------------------
__global__ __launch_bounds__(256)
void k_scan_v(const float* __restrict__ src, float* __restrict__ cat,
              const float* __restrict__ w_up, const float* __restrict__ b_up,
              const float* __restrict__ w_dn, const float* __restrict__ b_dn)
{
    int idx = blockIdx.x * 256 + threadIdx.x;
    int w = idx & 255;
    int c = (idx >> 8) & 63;
    int b = idx >> 14;

    const float* s  = src + (((size_t)b * 64 + c) << 16) + w;
    float* cu = cat + (((size_t)b * 256 +   0 + c) << 16) + w;
    float* cd = cat + (((size_t)b * 256 + 128 + c) << 16) + w;

    float Wd = w_dn[c], Bd = b_dn[c], Wu = w_up[c], Bu = b_up[c];

    float h = 0.f;
    for (int r = 0; r < 256; r++) {
        h = fmaxf(fmaf(Wd, h, s[r << 8] + Bd), 0.f);
        cd[r << 8] = h;
    }
    h = 0.f;
    for (int r = 255; r >= 0; r--) {
        h = fmaxf(fmaf(Wu, h, s[r << 8] + Bu), 0.f);
        cu[r << 8] = h;
    }
}

// ---------------------------------------------------------------------------
// Horizontal IRNN scans (right -> dir 1, left -> dir 3). One thread per (b,c,h).
// ---------------------------------------------------------------------------
__global__ __launch_bounds__(256)
void k_scan_h(const float* __restrict__ src, float* __restrict__ cat,
              const float* __restrict__ w_rt, const float* __restrict__ b_rt,
              const float* __restrict__ w_lt, const float* __restrict__ b_lt)
{
    int idx = blockIdx.x * 256 + threadIdx.x;
    int hrow = idx & 255;
    int c = (idx >> 8) & 63;
    int b = idx >> 14;

    const float* s  = src + (((size_t)b * 64 + c) << 16) + hrow * 256;
    float* cr = cat + (((size_t)b * 256 +  64 + c) << 16) + hrow * 256;
    float* cl = cat + (((size_t)b * 256 + 192 + c) << 16) + hrow * 256;

    float Wr = w_rt[c], Br = b_rt[c], Wl = w_lt[c], Bl = b_lt[c];

    float h = 0.f;
    for (int w = 0; w < 256; w++) {
        h = fmaxf(fmaf(Wr, h, s[w] + Br), 0.f);
        cr[w] = h;
    }
    h = 0.f;
    for (int w = 255; w >= 0; w--) {
        h = fmaxf(fmaf(Wl, h, s[w] + Bl), 0.f);
        cl[w] = h;
    }
}

// ---------------------------------------------------------------------------
// Final: a = a3_w . a2 + a3_b ; weight = sigmoid(a) ; out = relu(x * weight)
// ---------------------------------------------------------------------------
__global__ __launch_bounds__(256)
void k_final(const float* __restrict__ a2buf, const float* __restrict__ a3w,
             const float* __restrict__ a3b, const float* __restrict__ x,
             float* __restrict__ out)
{
    int p  = blockIdx.x * 256 + threadIdx.x;
    int b  = p >> 16;
    int hw = p & 65535;

    const float* ab = a2buf + ((size_t)b * 32) * HW + hw;
    float s = a3b[0];
#pragma unroll
    for (int c = 0; c < 32; c++)
        s = fmaf(a3w[c], ab[(size_t)c * HW], s);

    float wgt = 1.f / (1.f + expf(-s));

    const float* xb = x   + ((size_t)b * 64) * HW + hw;
    float*       ob = out + ((size_t)b * 64) * HW + hw;
#pragma unroll 8
    for (int c = 0; c < 64; c++)
        ob[(size_t)c * HW] = fmaxf(xb[(size_t)c * HW] * wgt, 0.f);
}

// ---------------------------------------------------------------------------
extern "C" void kernel_launch(void* const* d_in, const int* in_sizes, int n_in,
                              void* d_out, int out_size)
{
    const float* x       = (const float*)d_in[0];
    const float* w_in    = (const float*)d_in[1];
    const float* w_up    = (const float*)d_in[2];
    const float* b_up    = (const float*)d_in[3];
    const float* w_right = (const float*)d_in[4];
    const float* b_right = (const float*)d_in[5];
    const float* w_down  = (const float*)d_in[6];
    const float* b_down  = (const float*)d_in[7];
    const float* w_left  = (const float*)d_in[8];
    const float* b_left  = (const float*)d_in[9];
    const float* wD2     = (const float*)d_in[10];
    const float* a1_w    = (const float*)d_in[11];
    const float* a1_b    = (const float*)d_in[12];
    const float* a2_w    = (const float*)d_in[13];
    const float* a2_b    = (const float*)d_in[14];
    const float* a3_w    = (const float*)d_in[15];
    const float* a3_b    = (const float*)d_in[16];
    float* out = (float*)d_out;

    float *p_out1, *p_cat, *p_out2, *p_a1, *p_a2;
    cudaGetSymbolAddress((void**)&p_out1, g_out1);
    cudaGetSymbolAddress((void**)&p_cat,  g_cat);
    cudaGetSymbolAddress((void**)&p_out2, g_out2);
    cudaGetSymbolAddress((void**)&p_a1,   g_a1);
    cudaGetSymbolAddress((void**)&p_a2,   g_a2);

    dim3 gGemm(HW / 256, 1, BATCH);      // (256,1,4)
    dim3 gConv(256, 1, BATCH);

    // 1) out1 = conv1x1(x, w_in)                 (no relu)  -- TF32 MMA
    k_gemm_tc<64, false><<<gGemm, 256>>>(w_in, x, p_out1);

    // 2) four directional IRNN scans -> cat [b][4*64][h][w]
    k_scan_v<<<256, 256>>>(p_out1, p_cat, w_up, b_up, w_down, b_down);
    k_scan_h<<<256, 256>>>(p_out1, p_cat, w_right, b_right, w_left, b_left);

    // 3) out2 = relu(conv1x1(cat, wD2))          K = 256    -- TF32 MMA
    k_gemm_tc<256, true><<<gGemm, 256>>>(wD2, p_cat, p_out2);

    // 4) a1 = relu(conv3x3(out2, a1_w) + a1_b)              -- TF32 MMA implicit gemm
    k_conv3_tc<64><<<gConv, 256>>>(p_out2, a1_w, a1_b, p_a1);

    // 5) a2 = relu(conv3x3(a1, a2_w) + a2_b)                -- TF32 MMA implicit gemm
    k_conv3_tc<32><<<gConv, 256>>>(p_a1, a2_w, a2_b, p_a2);

    // 6) out = relu(x * sigmoid(a3_w . a2 + a3_b))
    k_final<<<HW * BATCH / 256, 256>>>(p_a2, a3_w, a3_b, x, out);
}

// round 6
// speedup vs baseline: 1.5606x; 1.1718x over previous
#include <cuda_runtime.h>
#include <math.h>

#define HW      65536
#define BATCH   4

// ---------------- scratch (device globals; no allocation allowed) ----------
__device__ float    g_out1[(size_t)BATCH * 64  * HW];   //  67 MB  conv1x1 #1 out (fp32)
__device__ unsigned g_catp[(size_t)BATCH * 128 * HW];   // 134 MB  cat, bf16x2-packed k-pairs
__device__ float    g_out2[(size_t)BATCH * 64  * HW];   //  67 MB
__device__ float    g_a1  [(size_t)BATCH * 32  * HW];   //  34 MB
__device__ float    g_a2  [(size_t)BATCH * 32  * HW];   //  34 MB

// ---------------- helpers ---------------------------------------------------
__device__ __forceinline__ unsigned f2tf(float f) {
    unsigned u;
    asm("cvt.rna.tf32.f32 %0, %1;" : "=r"(u) : "f"(f));
    return u;
}
// pack two fp32 -> bf16x2 register: low 16 bits = lo, high = hi
__device__ __forceinline__ unsigned packbf(float hi, float lo) {
    unsigned r;
    asm("cvt.rn.bf16x2.f32 %0, %1, %2;" : "=r"(r) : "f"(hi), "f"(lo));
    return r;
}
__device__ __forceinline__ void cpasync16(void* dst, const void* src) {
    unsigned d = (unsigned)__cvta_generic_to_shared(dst);
    asm volatile("cp.async.cg.shared.global [%0], [%1], 16;" :: "r"(d), "l"(src));
}

#define MMA_TF32(c, a, b0, b1)                                              \
    asm volatile("mma.sync.aligned.m16n8k8.row.col.f32.tf32.tf32.f32 "      \
        "{%0,%1,%2,%3}, {%4,%5,%6,%7}, {%8,%9}, {%0,%1,%2,%3};"             \
        : "+f"((c)[0]), "+f"((c)[1]), "+f"((c)[2]), "+f"((c)[3])            \
        : "r"((a)[0]), "r"((a)[1]), "r"((a)[2]), "r"((a)[3]),               \
          "r"(b0), "r"(b1))

#define MMA_BF16(c, a, b0, b1)                                              \
    asm volatile("mma.sync.aligned.m16n8k16.row.col.f32.bf16.bf16.f32 "     \
        "{%0,%1,%2,%3}, {%4,%5,%6,%7}, {%8,%9}, {%0,%1,%2,%3};"             \
        : "+f"((c)[0]), "+f"((c)[1]), "+f"((c)[2]), "+f"((c)[3])            \
        : "r"((a)[0]), "r"((a)[1]), "r"((a)[2]), "r"((a)[3]),               \
          "r"(b0), "r"(b1))

// ---------------------------------------------------------------------------
// TF32 GEMM for stage 1 (K=64): memory-bound; keeps scan input at fp32 quality.
// Block M64 x N256, Kchunk 32. grid (256,1,4).
// ---------------------------------------------------------------------------
template<int K, bool RELU>
__global__ __launch_bounds__(256)
void k_gemm_tc(const float* __restrict__ Wt, const float* __restrict__ X,
               float* __restrict__ Y)
{
    __shared__ unsigned ws[64 * 36];
    __shared__ unsigned xs[32 * 264];

    const int tid  = threadIdx.x;
    const int warp = tid >> 5;
    const int lane = tid & 31;
    const int n0   = blockIdx.x * 256;
    const int b    = blockIdx.z;
    const float* Xb = X + (size_t)b * K * HW;
    float*       Yb = Y + (size_t)b * 64 * HW;

    const int mw = (warp & 1) * 32;
    const int nw = (warp >> 1) * 64;
    const int qt = lane >> 2;
    const int rt = lane & 3;

    float acc[2][8][4];
#pragma unroll
    for (int i = 0; i < 2; i++)
#pragma unroll
        for (int j = 0; j < 8; j++)
#pragma unroll
            for (int v = 0; v < 4; v++) acc[i][j][v] = 0.f;

    for (int kt = 0; kt < K; kt += 32) {
#pragma unroll
        for (int r = 0; r < 8; r++) {
            int e  = tid + r * 256;
            int m  = e >> 5;
            int kk = e & 31;
            ws[m * 36 + kk] = f2tf(Wt[m * K + kt + kk]);
        }
#pragma unroll
        for (int r = 0; r < 8; r++) {
            int idx = r * 256 + tid;
            int k   = idx >> 6;
            int nf  = idx & 63;
            float4 v = *(const float4*)&Xb[(size_t)(kt + k) * HW + n0 + nf * 4];
            unsigned* d = &xs[k * 264 + nf * 4];
            d[0] = f2tf(v.x); d[1] = f2tf(v.y); d[2] = f2tf(v.z); d[3] = f2tf(v.w);
        }
        __syncthreads();

#pragma unroll
        for (int kk = 0; kk < 4; kk++) {
            const int kb = kk * 8;
            unsigned a[2][4];
#pragma unroll
            for (int mt = 0; mt < 2; mt++) {
                int mr = mw + mt * 16 + qt;
                int kc = kb + rt;
                a[mt][0] = ws[mr * 36 + kc];
                a[mt][1] = ws[(mr + 8) * 36 + kc];
                a[mt][2] = ws[mr * 36 + kc + 4];
                a[mt][3] = ws[(mr + 8) * 36 + kc + 4];
            }
#pragma unroll
            for (int nt = 0; nt < 8; nt++) {
                int col = nw + nt * 8 + qt;
                unsigned b0 = xs[(kb + rt) * 264 + col];
                unsigned b1 = xs[(kb + rt + 4) * 264 + col];
                MMA_TF32(acc[0][nt], a[0], b0, b1);
                MMA_TF32(acc[1][nt], a[1], b0, b1);
            }
        }
        __syncthreads();
    }

#pragma unroll
    for (int mt = 0; mt < 2; mt++) {
        int mr = mw + mt * 16 + qt;
#pragma unroll
        for (int nt = 0; nt < 8; nt++) {
            int col = n0 + nw + nt * 8 + rt * 2;
            float2 v0, v1;
            v0.x = acc[mt][nt][0]; v0.y = acc[mt][nt][1];
            v1.x = acc[mt][nt][2]; v1.y = acc[mt][nt][3];
            if (RELU) {
                v0.x = fmaxf(v0.x, 0.f); v0.y = fmaxf(v0.y, 0.f);
                v1.x = fmaxf(v1.x, 0.f); v1.y = fmaxf(v1.y, 0.f);
            }
            *(float2*)&Yb[(size_t)mr * HW + col]       = v0;
            *(float2*)&Yb[(size_t)(mr + 8) * HW + col] = v1;
        }
    }
}

// ---------------------------------------------------------------------------
// Fused 4-direction IRNN scans. Each thread handles TWO channels (a k-pair)
// and writes bf16x2-packed cat. Blocks 0..127: vertical; 128..255: horizontal.
// cat k layout: up = [0,64), right = [64,128), down = [128,192), left = [192,256)
// packed k2 = k/2.
// ---------------------------------------------------------------------------
__global__ __launch_bounds__(256)
void k_scans(const float* __restrict__ src, unsigned* __restrict__ catp,
             const float* __restrict__ w_up, const float* __restrict__ b_up,
             const float* __restrict__ w_rt, const float* __restrict__ b_rt,
             const float* __restrict__ w_dn, const float* __restrict__ b_dn,
             const float* __restrict__ w_lt, const float* __restrict__ b_lt)
{
    const bool vert = blockIdx.x < 128;
    int idx = (vert ? blockIdx.x : blockIdx.x - 128) * 256 + threadIdx.x; // [0,32768)
    int p  = idx & 255;            // w (vert) or h (horz)
    int c2 = (idx >> 8) & 31;
    int b  = idx >> 13;
    int c  = c2 * 2;

    if (vert) {
        const float* s0 = src + (((size_t)b * 64 + c) << 16) + p;
        const float* s1 = s0 + HW;
        unsigned* cu = catp + (((size_t)b * 128 +      c2) << 16) + p;  // up
        unsigned* cd = catp + (((size_t)b * 128 + 64 + c2) << 16) + p;  // down
        float W0 = w_dn[c], W1 = w_dn[c + 1], B0 = b_dn[c], B1 = b_dn[c + 1];
        float h0 = 0.f, h1 = 0.f;
        for (int r = 0; r < 256; r++) {
            h0 = fmaxf(fmaf(W0, h0, s0[r << 8] + B0), 0.f);
            h1 = fmaxf(fmaf(W1, h1, s1[r << 8] + B1), 0.f);
            cd[r << 8] = packbf(h1, h0);
        }
        W0 = w_up[c]; W1 = w_up[c + 1]; B0 = b_up[c]; B1 = b_up[c + 1];
        h0 = 0.f; h1 = 0.f;
        for (int r = 255; r >= 0; r--) {
            h0 = fmaxf(fmaf(W0, h0, s0[r << 8] + B0), 0.f);
            h1 = fmaxf(fmaf(W1, h1, s1[r << 8] + B1), 0.f);
            cu[r << 8] = packbf(h1, h0);
        }
    } else {
        const float* s0 = src + (((size_t)b * 64 + c) << 16) + p * 256;
        const float* s1 = s0 + HW;
        unsigned* cr = catp + (((size_t)b * 128 + 32 + c2) << 16) + p * 256;  // right
        unsigned* cl = catp + (((size_t)b * 128 + 96 + c2) << 16) + p * 256;  // left
        float W0 = w_rt[c], W1 = w_rt[c + 1], B0 = b_rt[c], B1 = b_rt[c + 1];
        float h0 = 0.f, h1 = 0.f;
        for (int w = 0; w < 256; w++) {
            h0 = fmaxf(fmaf(W0, h0, s0[w] + B0), 0.f);
            h1 = fmaxf(fmaf(W1, h1, s1[w] + B1), 0.f);
            cr[w] = packbf(h1, h0);
        }
        W0 = w_lt[c]; W1 = w_lt[c + 1]; B0 = b_lt[c]; B1 = b_lt[c + 1];
        h0 = 0.f; h1 = 0.f;
        for (int w = 255; w >= 0; w--) {
            h0 = fmaxf(fmaf(W0, h0, s0[w] + B0), 0.f);
            h1 = fmaxf(fmaf(W1, h1, s1[w] + B1), 0.f);
            cl[w] = packbf(h1, h0);
        }
    }
}

// ---------------------------------------------------------------------------
// BF16 tensor-core GEMM for stage 3: out2 = relu(wD2 @ cat), K=256.
// B read pre-packed bf16x2 from g_catp via cp.async (double-buffered).
// A (fp32 wD2) software-pipelined through registers with bf16 conversion.
// Block M64 x N256, Kchunk 32 (16 k2 rows). 8 warps; warp = M64 x N32.
// grid (256,1,4).
// ---------------------------------------------------------------------------
__global__ __launch_bounds__(256)
void k_gemm256_bf16(const float* __restrict__ Wt, const unsigned* __restrict__ Xp,
                    float* __restrict__ Y)
{
    __shared__ unsigned ws[2][64 * 20];   // [m][k2] stride 20 (conflict-free frags)
    __shared__ unsigned xs[2][16 * 260];  // [k2][n] stride 260 (1040B, 16B-aligned)

    const int tid  = threadIdx.x;
    const int warp = tid >> 5;
    const int lane = tid & 31;
    const int n0   = blockIdx.x * 256;
    const int b    = blockIdx.z;
    const unsigned* Xb = Xp + (size_t)b * 128 * HW;
    float*          Yb = Y  + (size_t)b * 64 * HW;

    const int nw = warp * 32;
    const int qt = lane >> 2;
    const int rt = lane & 3;

    float acc[4][4][4];
#pragma unroll
    for (int i = 0; i < 4; i++)
#pragma unroll
        for (int j = 0; j < 4; j++)
#pragma unroll
            for (int v = 0; v < 4; v++) acc[i][j][v] = 0.f;

    // ---- prologue: stage chunk 0 ----
#pragma unroll
    for (int i = 0; i < 4; i++) {
        int e = tid + i * 256, m = e >> 4, l2 = e & 15;
        const float* pw = Wt + m * 256 + 2 * l2;
        ws[0][m * 20 + l2] = packbf(pw[1], pw[0]);
    }
#pragma unroll
    for (int j = 0; j < 4; j++) {
        int idx = tid + j * 256, row = idx >> 6, col = (idx & 63) * 4;
        cpasync16(&xs[0][row * 260 + col], Xb + (size_t)row * HW + n0 + col);
    }
    asm volatile("cp.async.commit_group;");
    asm volatile("cp.async.wait_group 0;");
    __syncthreads();

    for (int kt = 0; kt < 8; kt++) {
        const int cur = kt & 1, nxt = cur ^ 1;
        float aw0[4], aw1[4];
        if (kt < 7) {
#pragma unroll
            for (int j = 0; j < 4; j++) {
                int idx = tid + j * 256, row = idx >> 6, col = (idx & 63) * 4;
                cpasync16(&xs[nxt][row * 260 + col],
                          Xb + (size_t)((kt + 1) * 16 + row) * HW + n0 + col);
            }
            asm volatile("cp.async.commit_group;");
#pragma unroll
            for (int i = 0; i < 4; i++) {
                int e = tid + i * 256, m = e >> 4, l2 = e & 15;
                const float* pw = Wt + m * 256 + (kt + 1) * 32 + 2 * l2;
                aw0[i] = pw[0]; aw1[i] = pw[1];
            }
        }

        // ---- compute chunk: 2 x k16 steps ----
#pragma unroll
        for (int s = 0; s < 2; s++) {
            const int kb = s * 8;
            unsigned a[4][4];
#pragma unroll
            for (int mt = 0; mt < 4; mt++) {
                int m = mt * 16 + qt;
                a[mt][0] = ws[cur][m * 20 + kb + rt];
                a[mt][1] = ws[cur][(m + 8) * 20 + kb + rt];
                a[mt][2] = ws[cur][m * 20 + kb + rt + 4];
                a[mt][3] = ws[cur][(m + 8) * 20 + kb + rt + 4];
            }
#pragma unroll
            for (int nt = 0; nt < 4; nt++) {
                int col = nw + nt * 8 + qt;
                unsigned b0 = xs[cur][(kb + rt) * 260 + col];
                unsigned b1 = xs[cur][(kb + rt + 4) * 260 + col];
#pragma unroll
                for (int mt = 0; mt < 4; mt++)
                    MMA_BF16(acc[mt][nt], a[mt], b0, b1);
            }
        }

        if (kt < 7) {
#pragma unroll
            for (int i = 0; i < 4; i++) {
                int e = tid + i * 256, m = e >> 4, l2 = e & 15;
                ws[nxt][m * 20 + l2] = packbf(aw1[i], aw0[i]);
            }
            asm volatile("cp.async.wait_group 0;");
        }
        __syncthreads();
    }

    // ---- epilogue: relu + float2 stores ----
#pragma unroll
    for (int mt = 0; mt < 4; mt++) {
        int mr = mt * 16 + qt;
#pragma unroll
        for (int nt = 0; nt < 4; nt++) {
            int col = n0 + nw + nt * 8 + rt * 2;
            float2 v0, v1;
            v0.x = fmaxf(acc[mt][nt][0], 0.f); v0.y = fmaxf(acc[mt][nt][1], 0.f);
            v1.x = fmaxf(acc[mt][nt][2], 0.f); v1.y = fmaxf(acc[mt][nt][3], 0.f);
            *(float2*)&Yb[(size_t)mr * HW + col]       = v0;
            *(float2*)&Yb[(size_t)(mr + 8) * HW + col] = v1;
        }
    }
}

// ---------------------------------------------------------------------------
// BF16 3x3 conv (SAME), CI -> 32 channels, relu(out + bias).
// Implicit GEMM, 2 output rows per block, chunks of 16 input channels.
// Block: 256 thr (8 warps); warp = (row, 64-px strip), M32 x N64.
// grid (128, 1, 4).
// ---------------------------------------------------------------------------
template<int CI>
__global__ __launch_bounds__(256)
void k_conv3_bf16(const float* __restrict__ in, const float* __restrict__ wt,
                  const float* __restrict__ bias, float* __restrict__ out)
{
    __shared__ unsigned xs[8 * 4 * 266];  // [i2][row(4)][col] packed ch-pairs
    __shared__ unsigned ws[9 * 8 * 36];   // [tap][i2][o] packed weight pairs

    const int h0    = blockIdx.x * 2;
    const int b     = blockIdx.z;
    const int tid   = threadIdx.x;
    const int warp  = tid >> 5;
    const int lane  = tid & 31;
    const int rw    = warp >> 2;          // 0/1: which output row
    const int strip = (warp & 3) * 64;
    const int qt    = lane >> 2;
    const int rt    = lane & 3;

    const float* inb = in + (size_t)b * CI * HW;

    float acc[2][8][4];
#pragma unroll
    for (int i = 0; i < 2; i++)
#pragma unroll
        for (int j = 0; j < 8; j++)
#pragma unroll
            for (int v = 0; v < 4; v++) acc[i][j][v] = 0.f;

    for (int i0 = 0; i0 < CI; i0 += 16) {
        // stage input: 16 channels (8 pairs) x 4 halo rows x cols -1..256
        for (int e = tid; e < 8 * 4 * 264; e += 256) {
            int i2  = e / 1056;
            int rem = e - i2 * 1056;
            int r   = rem / 264;
            int col = rem - r * 264;
            int hh  = h0 + r - 1;
            int ww  = col - 1;
            float v0 = 0.f, v1 = 0.f;
            if (col < 258 && (unsigned)hh < 256u && (unsigned)ww < 256u) {
                const float* p = inb + (size_t)(i0 + 2 * i2) * HW + hh * 256 + ww;
                v0 = p[0]; v1 = p[HW];
            }
            xs[(i2 * 4 + r) * 266 + col] = packbf(v1, v0);
        }
        // stage weights: ws[tap][i2][o] = pack(wt[o][i0+2i2+1][tap], wt[o][i0+2i2][tap])
        for (int e = tid; e < 9 * 8 * 32; e += 256) {
            int tap = e >> 8;
            int rem = e & 255;
            int i2  = rem >> 5;
            int o   = rem & 31;
            const float* p = wt + ((size_t)o * CI + i0 + 2 * i2) * 9 + tap;
            ws[(tap * 8 + i2) * 36 + o] = packbf(p[9], p[0]);
        }
        __syncthreads();

#pragma unroll
        for (int tap = 0; tap < 9; tap++) {
            const int r = tap / 3, c = tap % 3;
            unsigned a[2][4];
#pragma unroll
            for (int mt = 0; mt < 2; mt++) {
                int o = mt * 16 + qt;
                a[mt][0] = ws[(tap * 8 + rt) * 36 + o];
                a[mt][1] = ws[(tap * 8 + rt) * 36 + o + 8];
                a[mt][2] = ws[(tap * 8 + rt + 4) * 36 + o];
                a[mt][3] = ws[(tap * 8 + rt + 4) * 36 + o + 8];
            }
            const int rowidx = rw + r;
#pragma unroll
            for (int nt = 0; nt < 8; nt++) {
                int col = strip + nt * 8 + qt + c;
                unsigned b0 = xs[(rt * 4 + rowidx) * 266 + col];
                unsigned b1 = xs[((rt + 4) * 4 + rowidx) * 266 + col];
                MMA_BF16(acc[0][nt], a[0], b0, b1);
                MMA_BF16(acc[1][nt], a[1], b0, b1);
            }
        }
        __syncthreads();
    }

    // epilogue: bias + relu
    const int orow = (h0 + rw) * 256;
#pragma unroll
    for (int mt = 0; mt < 2; mt++) {
        int o = mt * 16 + qt;
        float bv0 = bias[o];
        float bv1 = bias[o + 8];
#pragma unroll
        for (int nt = 0; nt < 8; nt++) {
            int col = strip + nt * 8 + rt * 2;
            float2 v0, v1;
            v0.x = fmaxf(acc[mt][nt][0] + bv0, 0.f);
            v0.y = fmaxf(acc[mt][nt][1] + bv0, 0.f);
            v1.x = fmaxf(acc[mt][nt][2] + bv1, 0.f);
            v1.y = fmaxf(acc[mt][nt][3] + bv1, 0.f);
            *(float2*)&out[((size_t)(b * 32 + o))     * HW + orow + col] = v0;
            *(float2*)&out[((size_t)(b * 32 + o + 8)) * HW + orow + col] = v1;
        }
    }
}

// ---------------------------------------------------------------------------
// Final: a = a3_w . a2 + a3_b ; weight = sigmoid(a) ; out = relu(x * weight)
// float4-vectorized: 4 pixels per thread.
// ---------------------------------------------------------------------------
__global__ __launch_bounds__(256)
void k_final4(const float* __restrict__ a2buf, const float* __restrict__ a3w,
              const float* __restrict__ a3b, const float* __restrict__ x,
              float* __restrict__ out)
{
    int t   = blockIdx.x * 256 + threadIdx.x;    // [0, 65536)
    int b   = t >> 14;
    int hw  = (t & 16383) * 4;

    const float* ab = a2buf + ((size_t)b * 32) * HW + hw;
    float bv = a3b[0];
    float4 s = {bv, bv, bv, bv};
#pragma unroll
    for (int c = 0; c < 32; c++) {
        float4 v = *(const float4*)&ab[(size_t)c * HW];
        float w = a3w[c];
        s.x = fmaf(w, v.x, s.x); s.y = fmaf(w, v.y, s.y);
        s.z = fmaf(w, v.z, s.z); s.w = fmaf(w, v.w, s.w);
    }
    float4 g;
    g.x = 1.f / (1.f + expf(-s.x));
    g.y = 1.f / (1.f + expf(-s.y));
    g.z = 1.f / (1.f + expf(-s.z));
    g.w = 1.f / (1.f + expf(-s.w));

    const float* xb = x   + ((size_t)b * 64) * HW + hw;
    float*       ob = out + ((size_t)b * 64) * HW + hw;
#pragma unroll 8
    for (int c = 0; c < 64; c++) {
        float4 v = *(const float4*)&xb[(size_t)c * HW];
        float4 r;
        r.x = fmaxf(v.x * g.x, 0.f);
        r.y = fmaxf(v.y * g.y, 0.f);
        r.z = fmaxf(v.z * g.z, 0.f);
        r.w = fmaxf(v.w * g.w, 0.f);
        *(float4*)&ob[(size_t)c * HW] = r;
    }
}

// ---------------------------------------------------------------------------
extern "C" void kernel_launch(void* const* d_in, const int* in_sizes, int n_in,
                              void* d_out, int out_size)
{
    const float* x       = (const float*)d_in[0];
    const float* w_in    = (const float*)d_in[1];
    const float* w_up    = (const float*)d_in[2];
    const float* b_up    = (const float*)d_in[3];
    const float* w_right = (const float*)d_in[4];
    const float* b_right = (const float*)d_in[5];
    const float* w_down  = (const float*)d_in[6];
    const float* b_down  = (const float*)d_in[7];
    const float* w_left  = (const float*)d_in[8];
    const float* b_left  = (const float*)d_in[9];
    const float* wD2     = (const float*)d_in[10];
    const float* a1_w    = (const float*)d_in[11];
    const float* a1_b    = (const float*)d_in[12];
    const float* a2_w    = (const float*)d_in[13];
    const float* a2_b    = (const float*)d_in[14];
    const float* a3_w    = (const float*)d_in[15];
    const float* a3_b    = (const float*)d_in[16];
    float* out = (float*)d_out;

    float *p_out1, *p_out2, *p_a1, *p_a2;
    unsigned *p_catp;
    cudaGetSymbolAddress((void**)&p_out1, g_out1);
    cudaGetSymbolAddress((void**)&p_catp, g_catp);
    cudaGetSymbolAddress((void**)&p_out2, g_out2);
    cudaGetSymbolAddress((void**)&p_a1,   g_a1);
    cudaGetSymbolAddress((void**)&p_a2,   g_a2);

    dim3 gGemm(HW / 256, 1, BATCH);      // (256,1,4)
    dim3 gConv(128, 1, BATCH);

    // 1) out1 = conv1x1(x, w_in)   (TF32, memory-bound, keeps scan precision)
    k_gemm_tc<64, false><<<gGemm, 256>>>(w_in, x, p_out1);

    // 2) fused 4-direction scans -> packed bf16 cat
    k_scans<<<256, 256>>>(p_out1, p_catp,
                          w_up, b_up, w_right, b_right,
                          w_down, b_down, w_left, b_left);

    // 3) out2 = relu(conv1x1(cat, wD2))   K=256, bf16 MMA + cp.async pipeline
    k_gemm256_bf16<<<gGemm, 256>>>(wD2, p_catp, p_out2);

    // 4) a1 = relu(conv3x3(out2, a1_w) + a1_b)   bf16 implicit GEMM
    k_conv3_bf16<64><<<gConv, 256>>>(p_out2, a1_w, a1_b, p_a1);

    // 5) a2 = relu(conv3x3(a1, a2_w) + a2_b)
    k_conv3_bf16<32><<<gConv, 256>>>(p_a1, a2_w, a2_b, p_a2);

    // 6) out = relu(x * sigmoid(a3_w . a2 + a3_b))
    k_final4<<<256, 256>>>(p_a2, a3_w, a3_b, x, out);
}